// round 15
// baseline (speedup 1.0000x reference)
#include <cuda_runtime.h>
#include <cuda_bf16.h>

// ---------------- problem constants ----------------
#define BB   4
#define CDIM 64
#define C2   128
#define HH   31        // post-downsample spatial
#define N1   961       // HH*HH
#define G1N  16
#define KF   240       // top-k patches
#define NT   960       // fine tokens = KF*4
#define H2   62
#define TOT  (BB*CDIM*H2*H2)   // 984064
#define M_BN 15376.0f          // BB*H2*H2
#define LOG2E 1.4426950408889634f

__device__ __forceinline__ float ex2(float x) {
    float r; asm("ex2.approx.f32 %0, %1;" : "=f"(r) : "f"(x)); return r;
}

// ---------------- scratch (static device globals; no allocs) ----------------
__device__ float buf_xd[BB*C2*N1];       // conv-down output (NCHW)
__device__ float buf_o [BB*C2*N1];       // coarse attn output (NCHW)
__device__ float buf_coarse[BB*G1N*N1];  // column sums of coarse attn (g<16)
__device__ int   buf_topk[BB*G1N*KF];
__device__ float buf_co[TOT];            // coarse_out
__device__ float buf_y [TOT];            // y = 2*coarse_out + scatter(fine attn)
__device__ float buf_z [TOT];            // raw conv output (reused dw then pw)
__device__ float buf_stat[256];          // [dw sum, dw sq, pw sum, pw sq] x 64ch

// ---------------- conv down: 64->128ch, k=4, stride=2, pad=0 ----------------
__global__ void __launch_bounds__(256) k_conv_down(
    const float* __restrict__ x, const float* __restrict__ w,
    const float* __restrict__ bias)
{
    __shared__ float sin_[32*4*64 + 16];   // 32 ci x 4 rows x 64 cols
    int y = blockIdx.x, b = blockIdx.y;
    int tid = threadIdx.x;

    // fused zero-init
    {
        int flat = (b*31 + y)*256 + tid;          // 0..31743
        if (flat < BB*G1N*N1) buf_coarse[flat] = 0.f;
        int flat2 = flat + 124*256;
        if (flat2 < BB*G1N*N1) buf_coarse[flat2] = 0.f;
        if (flat < 256) buf_stat[flat] = 0.f;
    }

    int c2 = tid >> 1, xh = tid & 1;
    int x0 = xh * 16, nx = xh ? 15 : 16;

    float acc[16];
    #pragma unroll
    for (int i = 0; i < 16; i++) acc[i] = 0.f;

    for (int ph = 0; ph < 2; ph++) {
        __syncthreads();
        for (int i = tid; i < 32*4*64; i += 256) {
            int ci = i >> 8; int rem = i & 255; int ky = rem >> 6; int xi = rem & 63;
            sin_[i] = x[((b*64 + ph*32 + ci)*64 + (2*y + ky))*64 + xi];
        }
        __syncthreads();
        for (int ci = 0; ci < 32; ci++) {
            #pragma unroll
            for (int ky = 0; ky < 4; ky++) {
                float4 w4 = *(const float4*)(w + (((c2*64 + ph*32 + ci)*4 + ky) << 2));
                const float4* ip = (const float4*)(sin_ + (ci*4 + ky)*64 + 2*x0);
                float in[36];
                #pragma unroll
                for (int j = 0; j < 9; j++) {
                    float4 v = ip[j];
                    in[4*j] = v.x; in[4*j+1] = v.y; in[4*j+2] = v.z; in[4*j+3] = v.w;
                }
                #pragma unroll
                for (int xx = 0; xx < 16; xx++) {
                    acc[xx] = fmaf(in[2*xx+0], w4.x, acc[xx]);
                    acc[xx] = fmaf(in[2*xx+1], w4.y, acc[xx]);
                    acc[xx] = fmaf(in[2*xx+2], w4.z, acc[xx]);
                    acc[xx] = fmaf(in[2*xx+3], w4.w, acc[xx]);
                }
            }
        }
    }
    float bb = bias[c2];
    for (int xx = 0; xx < nx; xx++)
        buf_xd[((b*C2 + c2)*HH + y)*HH + x0 + xx] = acc[xx] + bb;
}

// ---------------- coarse attention: R13 (R7 structure + ex2 prescale) ------
__global__ void __launch_bounds__(256) k_attn_coarse(
    const float* __restrict__ wqkv, const float* __restrict__ bqkv)
{
    int bg = blockIdx.x;
    int b = bg >> 5, g = bg & 31;
    __shared__ float4 sq[N1], sk[N1], sv[N1];
    __shared__ float swq[48], sbq[12];
    int tid = threadIdx.x;
    if (tid < 48) swq[tid] = wqkv[tid];
    if (tid < 12) sbq[tid] = bqkv[tid];
    __syncthreads();

    const float* base = buf_xd + (b*C2 + g*4)*N1;
    for (int n = tid; n < N1; n += 256) {
        float t0 = base[n], t1 = base[N1+n], t2 = base[2*N1+n], t3 = base[3*N1+n];
        float r[12];
        #pragma unroll
        for (int c = 0; c < 12; c++)
            r[c] = sbq[c] + t0*swq[c] + t1*swq[12+c] + t2*swq[24+c] + t3*swq[36+c];
        sq[n] = make_float4(r[0], r[1], r[2],  r[3]);
        sk[n] = make_float4(r[4]*LOG2E, r[5]*LOG2E, r[6]*LOG2E, r[7]*LOG2E);
        sv[n] = make_float4(r[8], r[9], r[10], r[11]);
    }
    __syncthreads();

    int warp = tid >> 5, lane = tid & 31;
    bool doCoarse = (g < G1N);
    float cpart[31];
    #pragma unroll
    for (int j = 0; j < 31; j++) cpart[j] = 0.f;

    float* obase = buf_o + (b*C2 + g*4)*N1;
    for (int p = warp; p <= 480; p += 8) {
        int n0 = 2*p, n1 = n0 + 1;
        bool h1 = (n1 < N1);
        float4 k0 = sk[n0];
        float4 k1 = sk[h1 ? n1 : n0];
        float s0[31], s1[31];
        float mx0 = -1e30f, mx1 = -1e30f;
        #pragma unroll
        for (int j = 0; j < 31; j++) {
            int m = lane + 32*j;
            if (m < N1) {
                float4 qm = sq[m];
                float d0 = k0.x*qm.x + k0.y*qm.y + k0.z*qm.z + k0.w*qm.w;
                float d1 = k1.x*qm.x + k1.y*qm.y + k1.z*qm.z + k1.w*qm.w;
                s0[j] = d0; s1[j] = d1;
                mx0 = fmaxf(mx0, d0);
                mx1 = fmaxf(mx1, d1);
            } else { s0[j] = -1e30f; s1[j] = -1e30f; }
        }
        #pragma unroll
        for (int o = 16; o; o >>= 1) {
            mx0 = fmaxf(mx0, __shfl_xor_sync(0xffffffffu, mx0, o));
            mx1 = fmaxf(mx1, __shfl_xor_sync(0xffffffffu, mx1, o));
        }
        float sum0 = 0.f, sum1 = 0.f;
        float4 oa0 = make_float4(0.f,0.f,0.f,0.f);
        float4 oa1 = make_float4(0.f,0.f,0.f,0.f);
        #pragma unroll
        for (int j = 0; j < 31; j++) {
            int m = lane + 32*j;
            if (m < N1) {
                float e0 = ex2(s0[j] - mx0);
                float e1 = ex2(s1[j] - mx1);
                s0[j] = e0; s1[j] = e1;
                sum0 += e0; sum1 += e1;
                float4 vm = sv[m];
                oa0.x = fmaf(e0, vm.x, oa0.x); oa0.y = fmaf(e0, vm.y, oa0.y);
                oa0.z = fmaf(e0, vm.z, oa0.z); oa0.w = fmaf(e0, vm.w, oa0.w);
                oa1.x = fmaf(e1, vm.x, oa1.x); oa1.y = fmaf(e1, vm.y, oa1.y);
                oa1.z = fmaf(e1, vm.z, oa1.z); oa1.w = fmaf(e1, vm.w, oa1.w);
            } else { s0[j] = 0.f; s1[j] = 0.f; }
        }
        #pragma unroll
        for (int o = 16; o; o >>= 1) {
            sum0  += __shfl_xor_sync(0xffffffffu, sum0,  o);
            sum1  += __shfl_xor_sync(0xffffffffu, sum1,  o);
            oa0.x += __shfl_xor_sync(0xffffffffu, oa0.x, o);
            oa0.y += __shfl_xor_sync(0xffffffffu, oa0.y, o);
            oa0.z += __shfl_xor_sync(0xffffffffu, oa0.z, o);
            oa0.w += __shfl_xor_sync(0xffffffffu, oa0.w, o);
            oa1.x += __shfl_xor_sync(0xffffffffu, oa1.x, o);
            oa1.y += __shfl_xor_sync(0xffffffffu, oa1.y, o);
            oa1.z += __shfl_xor_sync(0xffffffffu, oa1.z, o);
            oa1.w += __shfl_xor_sync(0xffffffffu, oa1.w, o);
        }
        float inv0 = __fdividef(1.0f, sum0);
        float inv1 = h1 ? __fdividef(1.0f, sum1) : 0.f;
        if (lane == 0) {
            obase[n0]       = oa0.x*inv0;
            obase[N1+n0]    = oa0.y*inv0;
            obase[2*N1+n0]  = oa0.z*inv0;
            obase[3*N1+n0]  = oa0.w*inv0;
            if (h1) {
                obase[n1]       = oa1.x*inv1;
                obase[N1+n1]    = oa1.y*inv1;
                obase[2*N1+n1]  = oa1.z*inv1;
                obase[3*N1+n1]  = oa1.w*inv1;
            }
        }
        if (doCoarse) {
            #pragma unroll
            for (int j = 0; j < 31; j++)
                cpart[j] += s0[j]*inv0 + s1[j]*inv1;
        }
    }
    if (doCoarse) {
        float* cb = buf_coarse + (b*G1N + g)*N1;
        #pragma unroll
        for (int j = 0; j < 31; j++) {
            int m = lane + 32*j;
            if (m < N1) atomicAdd(cb + m, cpart[j]);
        }
    }
}

// ---------------- fused: top-k (blocks 0..63) + conv_up (blocks 64..559) ----
__global__ void __launch_bounds__(256) k_mid(
    const float* __restrict__ w_up, const float* __restrict__ b_up)
{
    __shared__ __align__(16) char smem_raw[2*C2*36*4];   // 36864 B
    int tid = threadIdx.x;

    if (blockIdx.x < 64) {
        // ---- top-k via threshold binary search (set semantics) ----
        unsigned* keys   = (unsigned*)smem_raw;            // 961*4 = 3844
        int*      tielist = (int*)(smem_raw + 3844);       // 961*4 = 3844
        int*      red     = (int*)(smem_raw + 7688);       // 2*8*4 = 64
        int*      tiecnt  = (int*)(smem_raw + 7752);
        int*      ctr     = (int*)(smem_raw + 7756);
        int bg = blockIdx.x;
        int warp = tid >> 5, lane = tid & 31;
        const float* cb = buf_coarse + bg*N1;
        for (int m = tid; m < N1; m += 256) keys[m] = __float_as_uint(cb[m]);
        if (tid == 0) { *tiecnt = 0; *ctr = 0; }
        __syncthreads();

        unsigned lo = 0u, hi = 0x7F7FFFFFu;
        int par = 0;
        while (lo < hi) {
            unsigned mid = lo + ((hi - lo) >> 1) + 1u;
            int c = 0;
            for (int m = tid; m < N1; m += 256) c += (keys[m] >= mid);
            #pragma unroll
            for (int o = 16; o; o >>= 1) c += __shfl_xor_sync(0xffffffffu, c, o);
            if (lane == 0) red[par*8 + warp] = c;
            __syncthreads();
            c = red[par*8+0]+red[par*8+1]+red[par*8+2]+red[par*8+3]
              + red[par*8+4]+red[par*8+5]+red[par*8+6]+red[par*8+7];
            if (c >= KF) lo = mid; else hi = mid - 1u;
            par ^= 1;
        }
        int cg = 0;
        for (int m = tid; m < N1; m += 256) {
            unsigned k = keys[m];
            cg += (k > lo);
            if (k == lo) { int pz = atomicAdd(tiecnt, 1); tielist[pz] = m; }
        }
        #pragma unroll
        for (int o = 16; o; o >>= 1) cg += __shfl_xor_sync(0xffffffffu, cg, o);
        if (lane == 0) red[par*8 + warp] = cg;
        __syncthreads();
        int nG = red[par*8+0]+red[par*8+1]+red[par*8+2]+red[par*8+3]
               + red[par*8+4]+red[par*8+5]+red[par*8+6]+red[par*8+7];
        int remaining = KF - nG;
        int nt = *tiecnt;

        int* ob = buf_topk + bg*KF;
        for (int m = tid; m < N1; m += 256) {
            unsigned k = keys[m];
            bool take = (k > lo);
            if (k == lo) {
                int r = 0;
                for (int t = 0; t < nt; t++) r += (tielist[t] < m);
                take = (r < remaining);
            }
            if (take) ob[atomicAdd(ctr, 1)] = m;
        }
        return;
    }

    // ---- transposed conv (lhs_dil=2, pad=2, k=4): 256 thr = 32 c x 8 xe ----
    float* sin_ = (float*)smem_raw;       // [t][c2][36]; col 0 and 32..35 = 0
    int r = blockIdx.x - 64;              // 0..495
    int Y = r % 62; int t_ = r / 62; int b = t_ & 3; int zc = t_ >> 2;  // zc 0..1
    int ky0, iy0, ky1, iy1;
    if ((Y & 1) == 0) { ky0 = 0; iy0 = Y/2 - 1; ky1 = 2; iy1 = Y/2; }
    else              { ky0 = 1; iy0 = (Y-1)/2; ky1 = 3; iy1 = (Y+1)/2; }

    for (int i = tid; i < 2*C2*36; i += 256) {
        int t = i / (C2*36); int rem = i - t*(C2*36); int c2 = rem / 36; int sl = rem - c2*36;
        int iy = t ? iy1 : iy0;
        int ix = sl - 1;
        float v = 0.f;
        if (iy >= 0 && iy < HH && ix >= 0 && ix < HH)
            v = buf_o[((b*C2 + c2)*HH + iy)*HH + ix];
        sin_[i] = v;
    }
    __syncthreads();

    int c = zc*32 + (tid >> 3), xe = tid & 7;
    int x0 = xe * 8, nx = (xe == 7) ? 6 : 8;
    int ry0 = 3 - ky0, ry1 = 3 - ky1;
    int sb = x0 >> 1;                    // xe*4 (float4-aligned)

    float acc[8];
    #pragma unroll
    for (int i = 0; i < 8; i++) acc[i] = 0.f;

    for (int c2 = 0; c2 < C2; c2++) {
        const float* wrow = w_up + ((c2*64 + c)*4)*4;
        float4 wa = *(const float4*)(wrow + ry0*4);
        float4 wb = *(const float4*)(wrow + ry1*4);
        const float* r0 = sin_ + c2*36;
        const float* r1 = sin_ + (C2 + c2)*36;
        float ia[6], ib[6];
        {
            float4 t4 = *(const float4*)(r0+sb);
            ia[0]=t4.x; ia[1]=t4.y; ia[2]=t4.z; ia[3]=t4.w;
            float2 t2 = *(const float2*)(r0+sb+4);
            ia[4]=t2.x; ia[5]=t2.y;
            t4 = *(const float4*)(r1+sb);
            ib[0]=t4.x; ib[1]=t4.y; ib[2]=t4.z; ib[3]=t4.w;
            t2 = *(const float2*)(r1+sb+4);
            ib[4]=t2.x; ib[5]=t2.y;
        }
        #pragma unroll
        for (int xx = 0; xx < 8; xx++) {
            if ((xx & 1) == 0) {
                int j = xx >> 1;   // kx=0 -> w[3]; kx=2 -> w[1]
                acc[xx] = fmaf(ia[j],   wa.w, acc[xx]);
                acc[xx] = fmaf(ia[j+1], wa.y, acc[xx]);
                acc[xx] = fmaf(ib[j],   wb.w, acc[xx]);
                acc[xx] = fmaf(ib[j+1], wb.y, acc[xx]);
            } else {
                int j = (xx + 1) >> 1; // kx=1 -> w[2]; kx=3 -> w[0]
                acc[xx] = fmaf(ia[j],   wa.z, acc[xx]);
                acc[xx] = fmaf(ia[j+1], wa.x, acc[xx]);
                acc[xx] = fmaf(ib[j],   wb.z, acc[xx]);
                acc[xx] = fmaf(ib[j+1], wb.x, acc[xx]);
            }
        }
    }
    float bb = b_up[c];
    for (int xx = 0; xx < nx; xx++) {
        float v = acc[xx] + bb;
        int o = ((b*64 + c)*H2 + Y)*H2 + x0 + xx;
        buf_co[o] = v;
        buf_y[o]  = 2.f * v;
    }
}

// ---------------- fine attention: 128-thr blocks, 4 blocks/(b,g) ------------
// Register-file fix: 256-thr attention blocks at 222-255 regs exhaust the
// 64k-reg SM file -> only 1 block/SM ever resides (the true occupancy blocker
// since R7). 128 threads + __launch_bounds__(128,4) caps regs at 128 ->
// 4 blocks/SM = 16 warps/SM. Two-pass 2-row body (~110 regs) fits the cap.
__global__ void __launch_bounds__(128, 4) k_attn_fine(
    const float* __restrict__ wqkv, const float* __restrict__ bqkv)
{
    int blk = blockIdx.x;              // 256
    int bg = blk >> 2, quarter = blk & 3;
    int b = bg >> 4, g = bg & 15;
    __shared__ float4 sq[NT], sk[NT], sv[NT];
    __shared__ int sidx[KF];
    __shared__ float swq[48], sbq[12];
    int tid = threadIdx.x;
    if (tid < 48)  swq[tid]  = wqkv[tid];
    if (tid < 12)  sbq[tid]  = bqkv[tid];
    for (int t = tid; t < KF; t += 128) sidx[t] = buf_topk[(b*G1N + g)*KF + t];
    __syncthreads();

    for (int t = tid; t < NT; t += 128) {
        int kk = t >> 2, pix = t & 3;
        int i = pix >> 1, jj = pix & 1;
        int p = sidx[kk];
        int ph = p / HH, pw = p - ph*HH;
        int Yc = 2*ph + i, Xc = 2*pw + jj;
        const float* cbase = buf_co + ((b*64 + g*4)*H2 + Yc)*H2 + Xc;
        float t0 = cbase[0], t1 = cbase[H2*H2], t2 = cbase[2*H2*H2], t3 = cbase[3*H2*H2];
        float r[12];
        #pragma unroll
        for (int c = 0; c < 12; c++)
            r[c] = sbq[c] + t0*swq[c] + t1*swq[12+c] + t2*swq[24+c] + t3*swq[36+c];
        sq[t] = make_float4(r[0], r[1], r[2],  r[3]);
        sk[t] = make_float4(r[4]*LOG2E, r[5]*LOG2E, r[6]*LOG2E, r[7]*LOG2E);
        sv[t] = make_float4(r[8], r[9], r[10], r[11]);
    }
    __syncthreads();

    int warp = tid >> 5, lane = tid & 31;
    // 480 row pairs over 4 blocks x 4 warps: p = warp + 4*quarter, stride 16
    for (int p = warp + 4*quarter; p < 480; p += 16) {
        int n0 = 2*p, n1 = n0 + 1;
        float4 k0 = sk[n0];
        float4 k1 = sk[n1];
        float s0[30], s1[30];
        float mx0 = -1e30f, mx1 = -1e30f;
        #pragma unroll
        for (int j = 0; j < 30; j++) {
            int m = lane + 32*j;
            float4 qm = sq[m];
            float d0 = k0.x*qm.x + k0.y*qm.y + k0.z*qm.z + k0.w*qm.w;
            float d1 = k1.x*qm.x + k1.y*qm.y + k1.z*qm.z + k1.w*qm.w;
            s0[j] = d0; s1[j] = d1;
            mx0 = fmaxf(mx0, d0);
            mx1 = fmaxf(mx1, d1);
        }
        #pragma unroll
        for (int o = 16; o; o >>= 1) {
            mx0 = fmaxf(mx0, __shfl_xor_sync(0xffffffffu, mx0, o));
            mx1 = fmaxf(mx1, __shfl_xor_sync(0xffffffffu, mx1, o));
        }
        float sum0 = 0.f, sum1 = 0.f;
        float4 oa0 = make_float4(0.f,0.f,0.f,0.f);
        float4 oa1 = make_float4(0.f,0.f,0.f,0.f);
        #pragma unroll
        for (int j = 0; j < 30; j++) {
            int m = lane + 32*j;
            float e0 = ex2(s0[j] - mx0);
            float e1 = ex2(s1[j] - mx1);
            sum0 += e0; sum1 += e1;
            float4 vm = sv[m];
            oa0.x = fmaf(e0, vm.x, oa0.x); oa0.y = fmaf(e0, vm.y, oa0.y);
            oa0.z = fmaf(e0, vm.z, oa0.z); oa0.w = fmaf(e0, vm.w, oa0.w);
            oa1.x = fmaf(e1, vm.x, oa1.x); oa1.y = fmaf(e1, vm.y, oa1.y);
            oa1.z = fmaf(e1, vm.z, oa1.z); oa1.w = fmaf(e1, vm.w, oa1.w);
        }
        #pragma unroll
        for (int o = 16; o; o >>= 1) {
            sum0  += __shfl_xor_sync(0xffffffffu, sum0,  o);
            sum1  += __shfl_xor_sync(0xffffffffu, sum1,  o);
            oa0.x += __shfl_xor_sync(0xffffffffu, oa0.x, o);
            oa0.y += __shfl_xor_sync(0xffffffffu, oa0.y, o);
            oa0.z += __shfl_xor_sync(0xffffffffu, oa0.z, o);
            oa0.w += __shfl_xor_sync(0xffffffffu, oa0.w, o);
            oa1.x += __shfl_xor_sync(0xffffffffu, oa1.x, o);
            oa1.y += __shfl_xor_sync(0xffffffffu, oa1.y, o);
            oa1.z += __shfl_xor_sync(0xffffffffu, oa1.z, o);
            oa1.w += __shfl_xor_sync(0xffffffffu, oa1.w, o);
        }
        if (lane == 0) {
            float inv0 = __fdividef(1.0f, sum0);
            float inv1 = __fdividef(1.0f, sum1);
            #pragma unroll
            for (int rr = 0; rr < 2; rr++) {
                int n = rr ? n1 : n0;
                float4 oa = rr ? oa1 : oa0;
                float inv = rr ? inv1 : inv0;
                int kk = n >> 2, pix = n & 3;
                int i = pix >> 1, jj = pix & 1;
                int p2 = sidx[kk];
                int ph = p2 / HH, pw = p2 - ph*HH;
                int Yc = 2*ph + i, Xc = 2*pw + jj;
                float* yb = buf_y + ((b*64 + g*4)*H2 + Yc)*H2 + Xc;
                yb[0]        += oa.x*inv;
                yb[H2*H2]    += oa.y*inv;
                yb[2*H2*H2]  += oa.z*inv;
                yb[3*H2*H2]  += oa.w*inv;
            }
        }
    }
}

// ---------------- depthwise 3x3 conv (pad 1) + BN stats ----------------
__global__ void __launch_bounds__(256) k_dw(const float* __restrict__ w_dw) {
    int bc = blockIdx.x; int b = bc >> 6, c = bc & 63;
    __shared__ float sp[64*64];
    __shared__ float rs[16];
    int tid = threadIdx.x;
    for (int i = tid; i < 4096; i += 256) {
        int yy = i >> 6, xx = i & 63;
        float v = 0.f;
        if (yy >= 1 && yy <= 62 && xx >= 1 && xx <= 62)
            v = buf_y[((b*64 + c)*H2 + (yy-1))*H2 + (xx-1)];
        sp[i] = v;
    }
    float wr[9];
    #pragma unroll
    for (int i = 0; i < 9; i++) wr[i] = w_dw[c*9 + i];
    __syncthreads();

    float lsum = 0.f, lsq = 0.f;
    for (int i = tid; i < H2*H2; i += 256) {
        int Y = i / H2, X = i - Y*H2;
        float a = 0.f;
        #pragma unroll
        for (int ky = 0; ky < 3; ky++)
            #pragma unroll
            for (int kx = 0; kx < 3; kx++)
                a = fmaf(sp[(Y+ky)*64 + X+kx], wr[ky*3+kx], a);
        buf_z[((b*64 + c)*H2 + Y)*H2 + X] = a;
        lsum += a; lsq = fmaf(a, a, lsq);
    }
    #pragma unroll
    for (int o = 16; o; o >>= 1) {
        lsum += __shfl_xor_sync(0xffffffffu, lsum, o);
        lsq  += __shfl_xor_sync(0xffffffffu, lsq,  o);
    }
    int warp = tid >> 5, lane = tid & 31;
    if (lane == 0) { rs[warp] = lsum; rs[8+warp] = lsq; }
    __syncthreads();
    if (tid == 0) {
        float s = 0.f, q = 0.f;
        for (int i = 0; i < 8; i++) { s += rs[i]; q += rs[8+i]; }
        atomicAdd(&buf_stat[c],      s);
        atomicAdd(&buf_stat[64 + c], q);
    }
}

// ---------------- pointwise 1x1 conv (+fused BN1/relu6 on load) + BN stats --
__global__ void __launch_bounds__(256) k_pw(
    const float* __restrict__ w_pw,
    const float* __restrict__ g_dw, const float* __restrict__ be_dw)
{
    __shared__ float srow[64*H2 + 8];
    __shared__ float ssc[64], ssh[64];
    int Y = blockIdx.x, b = blockIdx.y;
    int tid = threadIdx.x;
    if (tid < 64) {
        float m = buf_stat[tid] * (1.0f / M_BN);
        float v = buf_stat[64 + tid] * (1.0f / M_BN) - m*m;
        float sc = g_dw[tid] * rsqrtf(v + 1e-5f);
        ssc[tid] = sc;
        ssh[tid] = be_dw[tid] - m*sc;
    }
    __syncthreads();
    for (int i = tid; i < 64*H2; i += 256) {
        int ci = i / H2, xx = i - ci*H2;
        float z = buf_z[((b*64 + ci)*H2 + Y)*H2 + xx];
        z = z * ssc[ci] + ssh[ci];
        srow[i] = fminf(fmaxf(z, 0.f), 6.f);
    }
    __syncthreads();
    int co = tid >> 2, xq = tid & 3;
    int x0 = xq * 16, nx = (xq == 3) ? 14 : 16;
    float acc[16];
    #pragma unroll
    for (int i = 0; i < 16; i++) acc[i] = 0.f;
    for (int ci = 0; ci < 64; ci++) {
        float w = w_pw[co*64 + ci];
        const float* r = srow + ci*H2 + x0;
        #pragma unroll
        for (int xx = 0; xx < 16; xx++) acc[xx] = fmaf(r[xx], w, acc[xx]);
    }
    float lsum = 0.f, lsq = 0.f;
    for (int xx = 0; xx < nx; xx++) {
        float a = acc[xx];
        buf_z[((b*64 + co)*H2 + Y)*H2 + x0 + xx] = a;
        lsum += a; lsq = fmaf(a, a, lsq);
    }
    lsum += __shfl_xor_sync(0xffffffffu, lsum, 1);
    lsum += __shfl_xor_sync(0xffffffffu, lsum, 2);
    lsq  += __shfl_xor_sync(0xffffffffu, lsq,  1);
    lsq  += __shfl_xor_sync(0xffffffffu, lsq,  2);
    if (xq == 0) {
        atomicAdd(&buf_stat[128 + co], lsum);
        atomicAdd(&buf_stat[192 + co], lsq);
    }
}

// ---------------- BN + relu6 stage 2: buf_z -> out (stats offset 128) ------
__global__ void k_bn2(float* __restrict__ dst,
                      const float* __restrict__ gam, const float* __restrict__ bet)
{
    int i4 = blockIdx.x * 256 + threadIdx.x;
    if (i4 >= TOT/4) return;
    int c = (i4 / 961) & 63;
    float m = buf_stat[128 + c] * (1.0f / M_BN);
    float v = buf_stat[192 + c] * (1.0f / M_BN) - m*m;
    float sc = gam[c] * rsqrtf(v + 1e-5f);
    float sh = bet[c] - m*sc;
    float4 z = *((const float4*)buf_z + i4);
    float4 o;
    o.x = fminf(fmaxf(z.x*sc + sh, 0.f), 6.f);
    o.y = fminf(fmaxf(z.y*sc + sh, 0.f), 6.f);
    o.z = fminf(fmaxf(z.z*sc + sh, 0.f), 6.f);
    o.w = fminf(fmaxf(z.w*sc + sh, 0.f), 6.f);
    ((float4*)dst)[i4] = o;
}

// ---------------- launch ----------------
extern "C" void kernel_launch(void* const* d_in, const int* in_sizes, int n_in,
                              void* d_out, int out_size)
{
    const float* x       = (const float*)d_in[0];
    const float* w_down  = (const float*)d_in[1];
    const float* b_down  = (const float*)d_in[2];
    const float* w_qkv_c = (const float*)d_in[3];
    const float* b_qkv_c = (const float*)d_in[4];
    const float* w_up    = (const float*)d_in[5];
    const float* b_up    = (const float*)d_in[6];
    const float* w_qkv_t = (const float*)d_in[7];
    const float* b_qkv_t = (const float*)d_in[8];
    const float* w_dw    = (const float*)d_in[9];
    const float* g_dw    = (const float*)d_in[10];
    const float* be_dw   = (const float*)d_in[11];
    const float* w_pw    = (const float*)d_in[12];
    const float* g_pw    = (const float*)d_in[13];
    const float* be_pw   = (const float*)d_in[14];
    float* out = (float*)d_out;

    k_conv_down<<<dim3(HH, BB), 256>>>(x, w_down, b_down);   // 1
    k_attn_coarse<<<BB*32, 256>>>(w_qkv_c, b_qkv_c);          // 2
    k_mid<<<64 + 62*BB*2, 256>>>(w_up, b_up);                 // 3 (topk + conv_up)
    k_attn_fine<<<BB*G1N*4, 128>>>(w_qkv_t, b_qkv_t);         // 4 (profiled)
    k_dw<<<BB*64, 256>>>(w_dw);                               // 5
    k_pw<<<dim3(H2, BB), 256>>>(w_pw, g_dw, be_dw);           // 6
    k_bn2<<<(TOT/4 + 255)/256, 256>>>(out, g_pw, be_pw);      // 7
}

// round 16
// speedup vs baseline: 1.2387x; 1.2387x over previous
#include <cuda_runtime.h>
#include <cuda_bf16.h>

// ---------------- problem constants ----------------
#define BB   4
#define CDIM 64
#define C2   128
#define HH   31        // post-downsample spatial
#define N1   961       // HH*HH
#define G1N  16
#define KF   240       // top-k patches
#define NT   960       // fine tokens = KF*4
#define H2   62
#define TOT  (BB*CDIM*H2*H2)   // 984064
#define M_BN 15376.0f          // BB*H2*H2
#define LOG2E 1.4426950408889634f

__device__ __forceinline__ float ex2(float x) {
    float r; asm("ex2.approx.f32 %0, %1;" : "=f"(r) : "f"(x)); return r;
}

// ---------------- scratch (static device globals; no allocs) ----------------
__device__ float buf_xd[BB*C2*N1];       // conv-down output (NCHW)
__device__ float buf_o [BB*C2*N1];       // coarse attn output (NCHW)
__device__ float buf_coarse[BB*G1N*N1];  // column sums of coarse attn (g<16)
__device__ int   buf_topk[BB*G1N*KF];
__device__ float buf_co[TOT];            // coarse_out
__device__ float buf_y [TOT];            // y = 2*coarse_out + scatter(fine attn)
__device__ float buf_z [TOT];            // raw conv output (reused dw then pw)
__device__ float buf_stat[256];          // [dw sum, dw sq, pw sum, pw sq] x 64ch

// ---------------- conv down v2: 64->128ch, k=4, stride=2, pad=0 -------------
// Occupancy fix: 124 blocks < 148 SMs left SMs idle. Now grid (62,4) = 248
// blocks (y, x-half); 256 thr = 128 c2 x 2 x-eighths, 8 outputs each.
// regs ~50, smem 18KB -> multi-block residency. Also zeroes buf_coarse/stat.
__global__ void __launch_bounds__(256) k_conv_down(
    const float* __restrict__ x, const float* __restrict__ w,
    const float* __restrict__ bias)
{
    __shared__ float sin_[32*4*36 + 16];   // 32 ci x 4 ky x 36 cols (zero-pad)
    int bx = blockIdx.x;                   // 0..61
    int y = bx >> 1, xh = bx & 1;
    int b = blockIdx.y;
    int tid = threadIdx.x;

    // fused zero-init (248 blocks x 256 = 63488 >= 61504)
    {
        int flat = (b*62 + bx)*256 + tid;
        if (flat < BB*G1N*N1) buf_coarse[flat] = 0.f;
        if (flat < 256)       buf_stat[flat]   = 0.f;
    }

    int c2 = tid >> 1, sub = tid & 1;
    int x0g = xh*16 + sub*8;                       // global output col start
    int nx = (xh == 1 && sub == 1) ? 7 : 8;        // col 31 doesn't exist
    int rbase = sub*16;                            // rel input col base in smem

    float acc[8];
    #pragma unroll
    for (int i = 0; i < 8; i++) acc[i] = 0.f;

    for (int ph = 0; ph < 2; ph++) {
        __syncthreads();
        for (int i = tid; i < 32*4*36; i += 256) {
            int ci = i / 144; int rem = i - ci*144; int ky = rem / 36; int sl = rem - ky*36;
            int icol = 32*xh + sl;
            float v = 0.f;
            if (icol < 64)
                v = x[((b*64 + ph*32 + ci)*64 + (2*y + ky))*64 + icol];
            sin_[i] = v;
        }
        __syncthreads();
        for (int ci = 0; ci < 32; ci++) {
            #pragma unroll
            for (int ky = 0; ky < 4; ky++) {
                float4 w4 = *(const float4*)(w + (((c2*64 + ph*32 + ci)*4 + ky) << 2));
                const float* row = sin_ + (ci*4 + ky)*36 + rbase;
                float in[18];
                {
                    float4 t4;
                    t4 = *(const float4*)(row);     in[0]=t4.x; in[1]=t4.y; in[2]=t4.z; in[3]=t4.w;
                    t4 = *(const float4*)(row+4);   in[4]=t4.x; in[5]=t4.y; in[6]=t4.z; in[7]=t4.w;
                    t4 = *(const float4*)(row+8);   in[8]=t4.x; in[9]=t4.y; in[10]=t4.z; in[11]=t4.w;
                    t4 = *(const float4*)(row+12);  in[12]=t4.x; in[13]=t4.y; in[14]=t4.z; in[15]=t4.w;
                    float2 t2 = *(const float2*)(row+16); in[16]=t2.x; in[17]=t2.y;
                }
                #pragma unroll
                for (int xx = 0; xx < 8; xx++) {
                    acc[xx] = fmaf(in[2*xx+0], w4.x, acc[xx]);
                    acc[xx] = fmaf(in[2*xx+1], w4.y, acc[xx]);
                    acc[xx] = fmaf(in[2*xx+2], w4.z, acc[xx]);
                    acc[xx] = fmaf(in[2*xx+3], w4.w, acc[xx]);
                }
            }
        }
    }
    float bb = bias[c2];
    for (int xx = 0; xx < nx; xx++)
        buf_xd[((b*C2 + c2)*HH + y)*HH + x0g + xx] = acc[xx] + bb;
}

// ---------------- coarse attention: R13 (R7 structure + ex2 prescale) ------
__global__ void __launch_bounds__(256) k_attn_coarse(
    const float* __restrict__ wqkv, const float* __restrict__ bqkv)
{
    int bg = blockIdx.x;
    int b = bg >> 5, g = bg & 31;
    __shared__ float4 sq[N1], sk[N1], sv[N1];
    __shared__ float swq[48], sbq[12];
    int tid = threadIdx.x;
    if (tid < 48) swq[tid] = wqkv[tid];
    if (tid < 12) sbq[tid] = bqkv[tid];
    __syncthreads();

    const float* base = buf_xd + (b*C2 + g*4)*N1;
    for (int n = tid; n < N1; n += 256) {
        float t0 = base[n], t1 = base[N1+n], t2 = base[2*N1+n], t3 = base[3*N1+n];
        float r[12];
        #pragma unroll
        for (int c = 0; c < 12; c++)
            r[c] = sbq[c] + t0*swq[c] + t1*swq[12+c] + t2*swq[24+c] + t3*swq[36+c];
        sq[n] = make_float4(r[0], r[1], r[2],  r[3]);
        sk[n] = make_float4(r[4]*LOG2E, r[5]*LOG2E, r[6]*LOG2E, r[7]*LOG2E);
        sv[n] = make_float4(r[8], r[9], r[10], r[11]);
    }
    __syncthreads();

    int warp = tid >> 5, lane = tid & 31;
    bool doCoarse = (g < G1N);
    float cpart[31];
    #pragma unroll
    for (int j = 0; j < 31; j++) cpart[j] = 0.f;

    float* obase = buf_o + (b*C2 + g*4)*N1;
    for (int p = warp; p <= 480; p += 8) {
        int n0 = 2*p, n1 = n0 + 1;
        bool h1 = (n1 < N1);
        float4 k0 = sk[n0];
        float4 k1 = sk[h1 ? n1 : n0];
        float s0[31], s1[31];
        float mx0 = -1e30f, mx1 = -1e30f;
        #pragma unroll
        for (int j = 0; j < 31; j++) {
            int m = lane + 32*j;
            if (m < N1) {
                float4 qm = sq[m];
                float d0 = k0.x*qm.x + k0.y*qm.y + k0.z*qm.z + k0.w*qm.w;
                float d1 = k1.x*qm.x + k1.y*qm.y + k1.z*qm.z + k1.w*qm.w;
                s0[j] = d0; s1[j] = d1;
                mx0 = fmaxf(mx0, d0);
                mx1 = fmaxf(mx1, d1);
            } else { s0[j] = -1e30f; s1[j] = -1e30f; }
        }
        #pragma unroll
        for (int o = 16; o; o >>= 1) {
            mx0 = fmaxf(mx0, __shfl_xor_sync(0xffffffffu, mx0, o));
            mx1 = fmaxf(mx1, __shfl_xor_sync(0xffffffffu, mx1, o));
        }
        float sum0 = 0.f, sum1 = 0.f;
        float4 oa0 = make_float4(0.f,0.f,0.f,0.f);
        float4 oa1 = make_float4(0.f,0.f,0.f,0.f);
        #pragma unroll
        for (int j = 0; j < 31; j++) {
            int m = lane + 32*j;
            if (m < N1) {
                float e0 = ex2(s0[j] - mx0);
                float e1 = ex2(s1[j] - mx1);
                s0[j] = e0; s1[j] = e1;
                sum0 += e0; sum1 += e1;
                float4 vm = sv[m];
                oa0.x = fmaf(e0, vm.x, oa0.x); oa0.y = fmaf(e0, vm.y, oa0.y);
                oa0.z = fmaf(e0, vm.z, oa0.z); oa0.w = fmaf(e0, vm.w, oa0.w);
                oa1.x = fmaf(e1, vm.x, oa1.x); oa1.y = fmaf(e1, vm.y, oa1.y);
                oa1.z = fmaf(e1, vm.z, oa1.z); oa1.w = fmaf(e1, vm.w, oa1.w);
            } else { s0[j] = 0.f; s1[j] = 0.f; }
        }
        #pragma unroll
        for (int o = 16; o; o >>= 1) {
            sum0  += __shfl_xor_sync(0xffffffffu, sum0,  o);
            sum1  += __shfl_xor_sync(0xffffffffu, sum1,  o);
            oa0.x += __shfl_xor_sync(0xffffffffu, oa0.x, o);
            oa0.y += __shfl_xor_sync(0xffffffffu, oa0.y, o);
            oa0.z += __shfl_xor_sync(0xffffffffu, oa0.z, o);
            oa0.w += __shfl_xor_sync(0xffffffffu, oa0.w, o);
            oa1.x += __shfl_xor_sync(0xffffffffu, oa1.x, o);
            oa1.y += __shfl_xor_sync(0xffffffffu, oa1.y, o);
            oa1.z += __shfl_xor_sync(0xffffffffu, oa1.z, o);
            oa1.w += __shfl_xor_sync(0xffffffffu, oa1.w, o);
        }
        float inv0 = __fdividef(1.0f, sum0);
        float inv1 = h1 ? __fdividef(1.0f, sum1) : 0.f;
        if (lane == 0) {
            obase[n0]       = oa0.x*inv0;
            obase[N1+n0]    = oa0.y*inv0;
            obase[2*N1+n0]  = oa0.z*inv0;
            obase[3*N1+n0]  = oa0.w*inv0;
            if (h1) {
                obase[n1]       = oa1.x*inv1;
                obase[N1+n1]    = oa1.y*inv1;
                obase[2*N1+n1]  = oa1.z*inv1;
                obase[3*N1+n1]  = oa1.w*inv1;
            }
        }
        if (doCoarse) {
            #pragma unroll
            for (int j = 0; j < 31; j++)
                cpart[j] += s0[j]*inv0 + s1[j]*inv1;
        }
    }
    if (doCoarse) {
        float* cb = buf_coarse + (b*G1N + g)*N1;
        #pragma unroll
        for (int j = 0; j < 31; j++) {
            int m = lane + 32*j;
            if (m < N1) atomicAdd(cb + m, cpart[j]);
        }
    }
}

// ---------------- fused: top-k (blocks 0..63) + conv_up (blocks 64..559) ----
__global__ void __launch_bounds__(256) k_mid(
    const float* __restrict__ w_up, const float* __restrict__ b_up)
{
    __shared__ __align__(16) char smem_raw[2*C2*36*4];   // 36864 B
    int tid = threadIdx.x;

    if (blockIdx.x < 64) {
        // ---- top-k via threshold binary search (set semantics) ----
        unsigned* keys   = (unsigned*)smem_raw;            // 961*4 = 3844
        int*      tielist = (int*)(smem_raw + 3844);       // 961*4 = 3844
        int*      red     = (int*)(smem_raw + 7688);       // 2*8*4 = 64
        int*      tiecnt  = (int*)(smem_raw + 7752);
        int*      ctr     = (int*)(smem_raw + 7756);
        int bg = blockIdx.x;
        int warp = tid >> 5, lane = tid & 31;
        const float* cb = buf_coarse + bg*N1;
        for (int m = tid; m < N1; m += 256) keys[m] = __float_as_uint(cb[m]);
        if (tid == 0) { *tiecnt = 0; *ctr = 0; }
        __syncthreads();

        unsigned lo = 0u, hi = 0x7F7FFFFFu;
        int par = 0;
        while (lo < hi) {
            unsigned mid = lo + ((hi - lo) >> 1) + 1u;
            int c = 0;
            for (int m = tid; m < N1; m += 256) c += (keys[m] >= mid);
            #pragma unroll
            for (int o = 16; o; o >>= 1) c += __shfl_xor_sync(0xffffffffu, c, o);
            if (lane == 0) red[par*8 + warp] = c;
            __syncthreads();
            c = red[par*8+0]+red[par*8+1]+red[par*8+2]+red[par*8+3]
              + red[par*8+4]+red[par*8+5]+red[par*8+6]+red[par*8+7];
            if (c >= KF) lo = mid; else hi = mid - 1u;
            par ^= 1;
        }
        int cg = 0;
        for (int m = tid; m < N1; m += 256) {
            unsigned k = keys[m];
            cg += (k > lo);
            if (k == lo) { int pz = atomicAdd(tiecnt, 1); tielist[pz] = m; }
        }
        #pragma unroll
        for (int o = 16; o; o >>= 1) cg += __shfl_xor_sync(0xffffffffu, cg, o);
        if (lane == 0) red[par*8 + warp] = cg;
        __syncthreads();
        int nG = red[par*8+0]+red[par*8+1]+red[par*8+2]+red[par*8+3]
               + red[par*8+4]+red[par*8+5]+red[par*8+6]+red[par*8+7];
        int remaining = KF - nG;
        int nt = *tiecnt;

        int* ob = buf_topk + bg*KF;
        for (int m = tid; m < N1; m += 256) {
            unsigned k = keys[m];
            bool take = (k > lo);
            if (k == lo) {
                int r = 0;
                for (int t = 0; t < nt; t++) r += (tielist[t] < m);
                take = (r < remaining);
            }
            if (take) ob[atomicAdd(ctr, 1)] = m;
        }
        return;
    }

    // ---- transposed conv (lhs_dil=2, pad=2, k=4): 256 thr = 32 c x 8 xe ----
    float* sin_ = (float*)smem_raw;       // [t][c2][36]; col 0 and 32..35 = 0
    int r = blockIdx.x - 64;              // 0..495
    int Y = r % 62; int t_ = r / 62; int b = t_ & 3; int zc = t_ >> 2;  // zc 0..1
    int ky0, iy0, ky1, iy1;
    if ((Y & 1) == 0) { ky0 = 0; iy0 = Y/2 - 1; ky1 = 2; iy1 = Y/2; }
    else              { ky0 = 1; iy0 = (Y-1)/2; ky1 = 3; iy1 = (Y+1)/2; }

    for (int i = tid; i < 2*C2*36; i += 256) {
        int t = i / (C2*36); int rem = i - t*(C2*36); int c2 = rem / 36; int sl = rem - c2*36;
        int iy = t ? iy1 : iy0;
        int ix = sl - 1;
        float v = 0.f;
        if (iy >= 0 && iy < HH && ix >= 0 && ix < HH)
            v = buf_o[((b*C2 + c2)*HH + iy)*HH + ix];
        sin_[i] = v;
    }
    __syncthreads();

    int c = zc*32 + (tid >> 3), xe = tid & 7;
    int x0 = xe * 8, nx = (xe == 7) ? 6 : 8;
    int ry0 = 3 - ky0, ry1 = 3 - ky1;
    int sb = x0 >> 1;                    // xe*4 (float4-aligned)

    float acc[8];
    #pragma unroll
    for (int i = 0; i < 8; i++) acc[i] = 0.f;

    for (int c2 = 0; c2 < C2; c2++) {
        const float* wrow = w_up + ((c2*64 + c)*4)*4;
        float4 wa = *(const float4*)(wrow + ry0*4);
        float4 wb = *(const float4*)(wrow + ry1*4);
        const float* r0 = sin_ + c2*36;
        const float* r1 = sin_ + (C2 + c2)*36;
        float ia[6], ib[6];
        {
            float4 t4 = *(const float4*)(r0+sb);
            ia[0]=t4.x; ia[1]=t4.y; ia[2]=t4.z; ia[3]=t4.w;
            float2 t2 = *(const float2*)(r0+sb+4);
            ia[4]=t2.x; ia[5]=t2.y;
            t4 = *(const float4*)(r1+sb);
            ib[0]=t4.x; ib[1]=t4.y; ib[2]=t4.z; ib[3]=t4.w;
            t2 = *(const float2*)(r1+sb+4);
            ib[4]=t2.x; ib[5]=t2.y;
        }
        #pragma unroll
        for (int xx = 0; xx < 8; xx++) {
            if ((xx & 1) == 0) {
                int j = xx >> 1;   // kx=0 -> w[3]; kx=2 -> w[1]
                acc[xx] = fmaf(ia[j],   wa.w, acc[xx]);
                acc[xx] = fmaf(ia[j+1], wa.y, acc[xx]);
                acc[xx] = fmaf(ib[j],   wb.w, acc[xx]);
                acc[xx] = fmaf(ib[j+1], wb.y, acc[xx]);
            } else {
                int j = (xx + 1) >> 1; // kx=1 -> w[2]; kx=3 -> w[0]
                acc[xx] = fmaf(ia[j],   wa.z, acc[xx]);
                acc[xx] = fmaf(ia[j+1], wa.x, acc[xx]);
                acc[xx] = fmaf(ib[j],   wb.z, acc[xx]);
                acc[xx] = fmaf(ib[j+1], wb.x, acc[xx]);
            }
        }
    }
    float bb = b_up[c];
    for (int xx = 0; xx < nx; xx++) {
        float v = acc[xx] + bb;
        int o = ((b*64 + c)*H2 + Y)*H2 + x0 + xx;
        buf_co[o] = v;
        buf_y[o]  = 2.f * v;
    }
}

// ---------------- fine attention: R13 exact (two-pass 2-row, 256 thr) -------
__global__ void __launch_bounds__(256) k_attn_fine(
    const float* __restrict__ wqkv, const float* __restrict__ bqkv)
{
    int blk = blockIdx.x;              // 128
    int bg = blk >> 1, half = blk & 1;
    int b = bg >> 4, g = bg & 15;
    __shared__ float4 sq[NT], sk[NT], sv[NT];
    __shared__ int sidx[KF];
    __shared__ float swq[48], sbq[12];
    int tid = threadIdx.x;
    if (tid < 48)  swq[tid]  = wqkv[tid];
    if (tid < 12)  sbq[tid]  = bqkv[tid];
    if (tid < KF)  sidx[tid] = buf_topk[(b*G1N + g)*KF + tid];
    __syncthreads();

    for (int t = tid; t < NT; t += 256) {
        int kk = t >> 2, pix = t & 3;
        int i = pix >> 1, jj = pix & 1;
        int p = sidx[kk];
        int ph = p / HH, pw = p - ph*HH;
        int Yc = 2*ph + i, Xc = 2*pw + jj;
        const float* cbase = buf_co + ((b*64 + g*4)*H2 + Yc)*H2 + Xc;
        float t0 = cbase[0], t1 = cbase[H2*H2], t2 = cbase[2*H2*H2], t3 = cbase[3*H2*H2];
        float r[12];
        #pragma unroll
        for (int c = 0; c < 12; c++)
            r[c] = sbq[c] + t0*swq[c] + t1*swq[12+c] + t2*swq[24+c] + t3*swq[36+c];
        sq[t] = make_float4(r[0], r[1], r[2],  r[3]);
        sk[t] = make_float4(r[4]*LOG2E, r[5]*LOG2E, r[6]*LOG2E, r[7]*LOG2E);
        sv[t] = make_float4(r[8], r[9], r[10], r[11]);
    }
    __syncthreads();

    int warp = tid >> 5, lane = tid & 31;
    for (int p = warp + 8*half; p < 480; p += 16) {
        int n0 = 2*p, n1 = n0 + 1;
        float4 k0 = sk[n0];
        float4 k1 = sk[n1];
        float s0[30], s1[30];
        float mx0 = -1e30f, mx1 = -1e30f;
        #pragma unroll
        for (int j = 0; j < 30; j++) {
            int m = lane + 32*j;
            float4 qm = sq[m];
            float d0 = k0.x*qm.x + k0.y*qm.y + k0.z*qm.z + k0.w*qm.w;
            float d1 = k1.x*qm.x + k1.y*qm.y + k1.z*qm.z + k1.w*qm.w;
            s0[j] = d0; s1[j] = d1;
            mx0 = fmaxf(mx0, d0);
            mx1 = fmaxf(mx1, d1);
        }
        #pragma unroll
        for (int o = 16; o; o >>= 1) {
            mx0 = fmaxf(mx0, __shfl_xor_sync(0xffffffffu, mx0, o));
            mx1 = fmaxf(mx1, __shfl_xor_sync(0xffffffffu, mx1, o));
        }
        float sum0 = 0.f, sum1 = 0.f;
        float4 oa0 = make_float4(0.f,0.f,0.f,0.f);
        float4 oa1 = make_float4(0.f,0.f,0.f,0.f);
        #pragma unroll
        for (int j = 0; j < 30; j++) {
            int m = lane + 32*j;
            float e0 = ex2(s0[j] - mx0);
            float e1 = ex2(s1[j] - mx1);
            sum0 += e0; sum1 += e1;
            float4 vm = sv[m];
            oa0.x = fmaf(e0, vm.x, oa0.x); oa0.y = fmaf(e0, vm.y, oa0.y);
            oa0.z = fmaf(e0, vm.z, oa0.z); oa0.w = fmaf(e0, vm.w, oa0.w);
            oa1.x = fmaf(e1, vm.x, oa1.x); oa1.y = fmaf(e1, vm.y, oa1.y);
            oa1.z = fmaf(e1, vm.z, oa1.z); oa1.w = fmaf(e1, vm.w, oa1.w);
        }
        #pragma unroll
        for (int o = 16; o; o >>= 1) {
            sum0  += __shfl_xor_sync(0xffffffffu, sum0,  o);
            sum1  += __shfl_xor_sync(0xffffffffu, sum1,  o);
            oa0.x += __shfl_xor_sync(0xffffffffu, oa0.x, o);
            oa0.y += __shfl_xor_sync(0xffffffffu, oa0.y, o);
            oa0.z += __shfl_xor_sync(0xffffffffu, oa0.z, o);
            oa0.w += __shfl_xor_sync(0xffffffffu, oa0.w, o);
            oa1.x += __shfl_xor_sync(0xffffffffu, oa1.x, o);
            oa1.y += __shfl_xor_sync(0xffffffffu, oa1.y, o);
            oa1.z += __shfl_xor_sync(0xffffffffu, oa1.z, o);
            oa1.w += __shfl_xor_sync(0xffffffffu, oa1.w, o);
        }
        if (lane == 0) {
            float inv0 = __fdividef(1.0f, sum0);
            float inv1 = __fdividef(1.0f, sum1);
            #pragma unroll
            for (int rr = 0; rr < 2; rr++) {
                int n = rr ? n1 : n0;
                float4 oa = rr ? oa1 : oa0;
                float inv = rr ? inv1 : inv0;
                int kk = n >> 2, pix = n & 3;
                int i = pix >> 1, jj = pix & 1;
                int p2 = sidx[kk];
                int ph = p2 / HH, pw = p2 - ph*HH;
                int Yc = 2*ph + i, Xc = 2*pw + jj;
                float* yb = buf_y + ((b*64 + g*4)*H2 + Yc)*H2 + Xc;
                yb[0]        += oa.x*inv;
                yb[H2*H2]    += oa.y*inv;
                yb[2*H2*H2]  += oa.z*inv;
                yb[3*H2*H2]  += oa.w*inv;
            }
        }
    }
}

// ---------------- depthwise 3x3 conv (pad 1) + BN stats ----------------
__global__ void __launch_bounds__(256) k_dw(const float* __restrict__ w_dw) {
    int bc = blockIdx.x; int b = bc >> 6, c = bc & 63;
    __shared__ float sp[64*64];
    __shared__ float rs[16];
    int tid = threadIdx.x;
    for (int i = tid; i < 4096; i += 256) {
        int yy = i >> 6, xx = i & 63;
        float v = 0.f;
        if (yy >= 1 && yy <= 62 && xx >= 1 && xx <= 62)
            v = buf_y[((b*64 + c)*H2 + (yy-1))*H2 + (xx-1)];
        sp[i] = v;
    }
    float wr[9];
    #pragma unroll
    for (int i = 0; i < 9; i++) wr[i] = w_dw[c*9 + i];
    __syncthreads();

    float lsum = 0.f, lsq = 0.f;
    for (int i = tid; i < H2*H2; i += 256) {
        int Y = i / H2, X = i - Y*H2;
        float a = 0.f;
        #pragma unroll
        for (int ky = 0; ky < 3; ky++)
            #pragma unroll
            for (int kx = 0; kx < 3; kx++)
                a = fmaf(sp[(Y+ky)*64 + X+kx], wr[ky*3+kx], a);
        buf_z[((b*64 + c)*H2 + Y)*H2 + X] = a;
        lsum += a; lsq = fmaf(a, a, lsq);
    }
    #pragma unroll
    for (int o = 16; o; o >>= 1) {
        lsum += __shfl_xor_sync(0xffffffffu, lsum, o);
        lsq  += __shfl_xor_sync(0xffffffffu, lsq,  o);
    }
    int warp = tid >> 5, lane = tid & 31;
    if (lane == 0) { rs[warp] = lsum; rs[8+warp] = lsq; }
    __syncthreads();
    if (tid == 0) {
        float s = 0.f, q = 0.f;
        for (int i = 0; i < 8; i++) { s += rs[i]; q += rs[8+i]; }
        atomicAdd(&buf_stat[c],      s);
        atomicAdd(&buf_stat[64 + c], q);
    }
}

// ---------------- pointwise 1x1 conv (+fused BN1/relu6 on load) + BN stats --
__global__ void __launch_bounds__(256) k_pw(
    const float* __restrict__ w_pw,
    const float* __restrict__ g_dw, const float* __restrict__ be_dw)
{
    __shared__ float srow[64*H2 + 8];
    __shared__ float ssc[64], ssh[64];
    int Y = blockIdx.x, b = blockIdx.y;
    int tid = threadIdx.x;
    if (tid < 64) {
        float m = buf_stat[tid] * (1.0f / M_BN);
        float v = buf_stat[64 + tid] * (1.0f / M_BN) - m*m;
        float sc = g_dw[tid] * rsqrtf(v + 1e-5f);
        ssc[tid] = sc;
        ssh[tid] = be_dw[tid] - m*sc;
    }
    __syncthreads();
    for (int i = tid; i < 64*H2; i += 256) {
        int ci = i / H2, xx = i - ci*H2;
        float z = buf_z[((b*64 + ci)*H2 + Y)*H2 + xx];
        z = z * ssc[ci] + ssh[ci];
        srow[i] = fminf(fmaxf(z, 0.f), 6.f);
    }
    __syncthreads();
    int co = tid >> 2, xq = tid & 3;
    int x0 = xq * 16, nx = (xq == 3) ? 14 : 16;
    float acc[16];
    #pragma unroll
    for (int i = 0; i < 16; i++) acc[i] = 0.f;
    for (int ci = 0; ci < 64; ci++) {
        float w = w_pw[co*64 + ci];
        const float* r = srow + ci*H2 + x0;
        #pragma unroll
        for (int xx = 0; xx < 16; xx++) acc[xx] = fmaf(r[xx], w, acc[xx]);
    }
    float lsum = 0.f, lsq = 0.f;
    for (int xx = 0; xx < nx; xx++) {
        float a = acc[xx];
        buf_z[((b*64 + co)*H2 + Y)*H2 + x0 + xx] = a;
        lsum += a; lsq = fmaf(a, a, lsq);
    }
    lsum += __shfl_xor_sync(0xffffffffu, lsum, 1);
    lsum += __shfl_xor_sync(0xffffffffu, lsum, 2);
    lsq  += __shfl_xor_sync(0xffffffffu, lsq,  1);
    lsq  += __shfl_xor_sync(0xffffffffu, lsq,  2);
    if (xq == 0) {
        atomicAdd(&buf_stat[128 + co], lsum);
        atomicAdd(&buf_stat[192 + co], lsq);
    }
}

// ---------------- BN + relu6 stage 2: buf_z -> out (stats offset 128) ------
__global__ void k_bn2(float* __restrict__ dst,
                      const float* __restrict__ gam, const float* __restrict__ bet)
{
    int i4 = blockIdx.x * 256 + threadIdx.x;
    if (i4 >= TOT/4) return;
    int c = (i4 / 961) & 63;
    float m = buf_stat[128 + c] * (1.0f / M_BN);
    float v = buf_stat[192 + c] * (1.0f / M_BN) - m*m;
    float sc = gam[c] * rsqrtf(v + 1e-5f);
    float sh = bet[c] - m*sc;
    float4 z = *((const float4*)buf_z + i4);
    float4 o;
    o.x = fminf(fmaxf(z.x*sc + sh, 0.f), 6.f);
    o.y = fminf(fmaxf(z.y*sc + sh, 0.f), 6.f);
    o.z = fminf(fmaxf(z.z*sc + sh, 0.f), 6.f);
    o.w = fminf(fmaxf(z.w*sc + sh, 0.f), 6.f);
    ((float4*)dst)[i4] = o;
}

// ---------------- launch ----------------
extern "C" void kernel_launch(void* const* d_in, const int* in_sizes, int n_in,
                              void* d_out, int out_size)
{
    const float* x       = (const float*)d_in[0];
    const float* w_down  = (const float*)d_in[1];
    const float* b_down  = (const float*)d_in[2];
    const float* w_qkv_c = (const float*)d_in[3];
    const float* b_qkv_c = (const float*)d_in[4];
    const float* w_up    = (const float*)d_in[5];
    const float* b_up    = (const float*)d_in[6];
    const float* w_qkv_t = (const float*)d_in[7];
    const float* b_qkv_t = (const float*)d_in[8];
    const float* w_dw    = (const float*)d_in[9];
    const float* g_dw    = (const float*)d_in[10];
    const float* be_dw   = (const float*)d_in[11];
    const float* w_pw    = (const float*)d_in[12];
    const float* g_pw    = (const float*)d_in[13];
    const float* be_pw   = (const float*)d_in[14];
    float* out = (float*)d_out;

    k_conv_down<<<dim3(62, BB), 256>>>(x, w_down, b_down);   // 1
    k_attn_coarse<<<BB*32, 256>>>(w_qkv_c, b_qkv_c);          // 2
    k_mid<<<64 + 62*BB*2, 256>>>(w_up, b_up);                 // 3 (topk + conv_up)
    k_attn_fine<<<BB*G1N*2, 256>>>(w_qkv_t, b_qkv_t);         // 4 (profiled)
    k_dw<<<BB*64, 256>>>(w_dw);                               // 5
    k_pw<<<dim3(H2, BB), 256>>>(w_pw, g_dw, be_dw);           // 6
    k_bn2<<<(TOT/4 + 255)/256, 256>>>(out, g_pw, be_pw);      // 7
}